// round 1
// baseline (speedup 1.0000x reference)
#include <cuda_runtime.h>
#include <cuda_bf16.h>
#include <cstdint>
#include <cstddef>

#define BATCH 128
#define SEQ   512
#define IND   768
#define HID   64

// Scratch (allocation-free rule: __device__ globals)
__device__ float g_pre0[BATCH * SEQ * HID];          // layer-0 pre-activations
__device__ unsigned short g_Whi[HID * IND];          // W_ih0 hi bf16 (truncated)
__device__ unsigned short g_Wlo[HID * IND];          // W_ih0 lo bf16 (rounded residual)

// ---------------------------------------------------------------------------
// Kernel 0: split W_ih0 into bf16 hi/lo
// ---------------------------------------------------------------------------
__global__ void split_w_kernel(const float* __restrict__ W) {
    int i = blockIdx.x * 256 + threadIdx.x;
    if (i < HID * IND) {
        float f = W[i];
        unsigned u = __float_as_uint(f) & 0xFFFF0000u;   // truncate-to-bf16 (exact split)
        g_Whi[i] = (unsigned short)(u >> 16);
        float lo = f - __uint_as_float(u);
        unsigned pair;
        asm("cvt.rn.bf16x2.f32 %0, %1, %2;" : "=r"(pair) : "f"(0.0f), "f"(lo));
        g_Wlo[i] = (unsigned short)(pair & 0xFFFFu);
    }
}

// ---------------------------------------------------------------------------
// Kernel 1: pre0 = x @ W_ih0^T + b_ih0 + b_hh0   via split-bf16 mma.sync
// M = 65536 (B*T), N = 64, K = 768. CTA: 64 M-rows, 4 warps (16 rows each).
// ---------------------------------------------------------------------------
__device__ __forceinline__ void split2(float2 f, uint32_t& hi, uint32_t& lo) {
    uint32_t u0 = __float_as_uint(f.x), u1 = __float_as_uint(f.y);
    hi = __byte_perm(u0, u1, 0x7632);                 // {bf16(f.y),bf16(f.x)} truncated
    float l0 = f.x - __uint_as_float(u0 & 0xFFFF0000u);
    float l1 = f.y - __uint_as_float(u1 & 0xFFFF0000u);
    asm("cvt.rn.bf16x2.f32 %0, %1, %2;" : "=r"(lo) : "f"(l1), "f"(l0));
}

#define MMA4(C, A, Bv)                                                          \
    asm volatile(                                                               \
        "mma.sync.aligned.m16n8k16.row.col.f32.bf16.bf16.f32 "                  \
        "{%0,%1,%2,%3}, {%4,%5,%6,%7}, {%8,%9}, {%0,%1,%2,%3};"                 \
        : "+f"((C)[0]), "+f"((C)[1]), "+f"((C)[2]), "+f"((C)[3])                \
        : "r"((A)[0]), "r"((A)[1]), "r"((A)[2]), "r"((A)[3]),                   \
          "r"((Bv)[0]), "r"((Bv)[1]))

__global__ __launch_bounds__(128) void input_gemm_kernel(
    const float* __restrict__ x,
    const float* __restrict__ bih, const float* __restrict__ bhh)
{
    int tid  = threadIdx.x;
    int warp = tid >> 5, lane = tid & 31;
    int g = lane >> 2, tg = lane & 3;
    int r0 = blockIdx.x * 64 + warp * 16 + g;
    int r1 = r0 + 8;
    const float* xr0 = x + (size_t)r0 * IND;
    const float* xr1 = x + (size_t)r1 * IND;

    float c[8][4];
#pragma unroll
    for (int nt = 0; nt < 8; nt++) { c[nt][0]=0.f; c[nt][1]=0.f; c[nt][2]=0.f; c[nt][3]=0.f; }

    for (int kc = 0; kc < IND; kc += 16) {
        uint32_t ah[4], al[4];
        split2(*(const float2*)(xr0 + kc     + tg*2), ah[0], al[0]);
        split2(*(const float2*)(xr1 + kc     + tg*2), ah[1], al[1]);
        split2(*(const float2*)(xr0 + kc + 8 + tg*2), ah[2], al[2]);
        split2(*(const float2*)(xr1 + kc + 8 + tg*2), ah[3], al[3]);
#pragma unroll
        for (int nt = 0; nt < 8; nt++) {
            int n = nt * 8 + g;
            const unsigned short* whp = g_Whi + n * IND + kc + tg * 2;
            const unsigned short* wlp = g_Wlo + n * IND + kc + tg * 2;
            uint32_t bh[2], bl[2];
            bh[0] = *(const uint32_t*)(whp);
            bh[1] = *(const uint32_t*)(whp + 8);
            bl[0] = *(const uint32_t*)(wlp);
            bl[1] = *(const uint32_t*)(wlp + 8);
            MMA4(c[nt], ah, bh);   // hi*hi
            MMA4(c[nt], al, bh);   // lo*hi
            MMA4(c[nt], ah, bl);   // hi*lo   (lo*lo dropped, ~2^-18)
        }
    }

#pragma unroll
    for (int nt = 0; nt < 8; nt++) {
        int n0 = nt * 8 + tg * 2;
        float bb0 = bih[n0]     + bhh[n0];
        float bb1 = bih[n0 + 1] + bhh[n0 + 1];
        float2 s0 = make_float2(c[nt][0] + bb0, c[nt][1] + bb1);
        float2 s1 = make_float2(c[nt][2] + bb0, c[nt][3] + bb1);
        *(float2*)(g_pre0 + (size_t)r0 * HID + n0) = s0;
        *(float2*)(g_pre0 + (size_t)r1 * HID + n0) = s1;
    }
}

// ---------------------------------------------------------------------------
// Kernel 2: fused 3-layer recurrence, one CTA per batch element.
// 128 threads: thread = 2*j + half; j = output neuron, half = k-range half.
// Weight row-slices live in registers as f32x2 pairs; h in smem (bank-safe).
// ---------------------------------------------------------------------------
typedef unsigned long long ull;

__device__ __forceinline__ ull fma2(ull a, ull b, ull c) {
    ull d; asm("fma.rn.f32x2 %0, %1, %2, %3;" : "=l"(d) : "l"(a), "l"(b), "l"(c)); return d;
}
__device__ __forceinline__ ull add2(ull a, ull b) {
    ull d; asm("add.rn.f32x2 %0, %1, %2;" : "=l"(d) : "l"(a), "l"(b)); return d;
}
__device__ __forceinline__ float red2(ull v) {
    float lo, hi; asm("mov.b64 {%0,%1}, %2;" : "=f"(lo), "=f"(hi) : "l"(v)); return lo + hi;
}
__device__ __forceinline__ ull packf2(float a, float b) {
    ull d; asm("mov.b64 %0, {%1,%2};" : "=l"(d) : "f"(a), "f"(b)); return d;
}

__device__ __forceinline__ void dot32acc(const ull* w, const float* hbase,
                                         ull& a0, ull& a1, ull& a2, ull& a3) {
    const ulonglong2* hp = (const ulonglong2*)hbase;   // 16B-aligned by layout
#pragma unroll
    for (int i = 0; i < 8; i += 2) {
        ulonglong2 u = hp[i];
        a0 = fma2(w[2*i],     u.x, a0);
        a1 = fma2(w[2*i + 1], u.y, a1);
        ulonglong2 v = hp[i + 1];
        a2 = fma2(w[2*i + 2], v.x, a2);
        a3 = fma2(w[2*i + 3], v.y, a3);
    }
}

__global__ __launch_bounds__(128, 1) void rnn_kernel(
    const float* __restrict__ Whh0,
    const float* __restrict__ Wih1, const float* __restrict__ Whh1,
    const float* __restrict__ bih1, const float* __restrict__ bhh1,
    const float* __restrict__ Wih2, const float* __restrict__ Whh2,
    const float* __restrict__ bih2, const float* __restrict__ bhh2,
    const float* __restrict__ fcw,  const float* __restrict__ fcb,
    float* __restrict__ out)
{
    // [layer][parity][half][36]: +36 floats between halves => broadcast groups
    // land in disjoint banks; each half-start is 16B aligned (144B stride).
    __shared__ float hs[3][2][2][36];

    int tid = threadIdx.x;
    int j = tid >> 1, half = tid & 1;
    int b = blockIdx.x;
    int jh = j >> 5, jl = j & 31;

    for (int i = tid; i < 3 * 2 * 2 * 36; i += 128) (&hs[0][0][0][0])[i] = 0.f;

    ull w0[16], wi1[16], wh1[16], wi2[16], wh2[16];
#define LOADW(dst, src) do {                                                    \
        const float4* p4 = (const float4*)((src) + j * HID + half * 32);        \
        _Pragma("unroll")                                                       \
        for (int i = 0; i < 8; i++) {                                           \
            float4 v = p4[i];                                                   \
            (dst)[2*i]     = packf2(v.x, v.y);                                  \
            (dst)[2*i + 1] = packf2(v.z, v.w);                                  \
        }                                                                       \
    } while (0)
    LOADW(w0,  Whh0);
    LOADW(wi1, Wih1);  LOADW(wh1, Whh1);
    LOADW(wi2, Wih2);  LOADW(wh2, Whh2);

    float bias1 = bih1[j] + bhh1[j];
    float bias2 = bih2[j] + bhh2[j];

    const float* preB = g_pre0 + (size_t)b * SEQ * HID;
    float pre_cur = preB[j];
    __syncthreads();

    for (int t = 0; t < SEQ; t++) {
        int p = t & 1, pn = p ^ 1;
        int tn = (t + 1 < SEQ) ? (t + 1) : (SEQ - 1);
        float pre_next = __ldg(preB + tn * HID + j);   // consumed next iter: full-step slack

        // ---- layer 0 ----
        ull a0 = 0, a1 = 0, a2 = 0, a3 = 0;
        dot32acc(w0, &hs[0][p][half][0], a0, a1, a2, a3);
        float d0 = red2(add2(add2(a0, a1), add2(a2, a3)));
        d0 += __shfl_xor_sync(0xFFFFFFFFu, d0, 1);
        float h0n = tanhf(pre_cur + d0);
        hs[0][pn][jh][jl] = h0n;
        __syncthreads();

        // ---- layer 1 ----
        a0 = 0; a1 = 0; a2 = 0; a3 = 0;
        dot32acc(wi1, &hs[0][pn][half][0], a0, a1, a2, a3);
        dot32acc(wh1, &hs[1][p][half][0],  a0, a1, a2, a3);
        float d1 = red2(add2(add2(a0, a1), add2(a2, a3)));
        d1 += __shfl_xor_sync(0xFFFFFFFFu, d1, 1);
        float h1n = tanhf(bias1 + d1);
        hs[1][pn][jh][jl] = h1n;
        __syncthreads();

        // ---- layer 2 ----
        a0 = 0; a1 = 0; a2 = 0; a3 = 0;
        dot32acc(wi2, &hs[1][pn][half][0], a0, a1, a2, a3);
        dot32acc(wh2, &hs[2][p][half][0],  a0, a1, a2, a3);
        float d2 = red2(add2(add2(a0, a1), add2(a2, a3)));
        d2 += __shfl_xor_sync(0xFFFFFFFFu, d2, 1);
        float h2n = tanhf(bias2 + d2);
        hs[2][pn][jh][jl] = h2n;
        __syncthreads();

        pre_cur = pre_next;
    }

    // final h2 (t=511 wrote parity 0) -> out[b] = fc_w . h2 + fc_b
    if (tid < 32) {
        float v0 = hs[2][0][0][tid];
        float v1 = hs[2][0][1][tid];
        float s = fcw[tid] * v0 + fcw[tid + 32] * v1;
#pragma unroll
        for (int o = 16; o; o >>= 1) s += __shfl_xor_sync(0xFFFFFFFFu, s, o);
        if (tid == 0) out[b] = s + fcb[0];
    }
}

// ---------------------------------------------------------------------------
// Launch: split W -> input GEMM -> fused recurrence (default stream, capturable)
// Input order: x, fixation_num, W_ih0, W_hh0, b_ih0, b_hh0, W_ih1, W_hh1,
//              b_ih1, b_hh1, W_ih2, W_hh2, b_ih2, b_hh2, fc_w, fc_b
// ---------------------------------------------------------------------------
extern "C" void kernel_launch(void* const* d_in, const int* in_sizes, int n_in,
                              void* d_out, int out_size)
{
    const float* x    = (const float*)d_in[0];
    const float* Wih0 = (const float*)d_in[2];
    const float* Whh0 = (const float*)d_in[3];
    const float* bih0 = (const float*)d_in[4];
    const float* bhh0 = (const float*)d_in[5];
    const float* Wih1 = (const float*)d_in[6];
    const float* Whh1 = (const float*)d_in[7];
    const float* bih1 = (const float*)d_in[8];
    const float* bhh1 = (const float*)d_in[9];
    const float* Wih2 = (const float*)d_in[10];
    const float* Whh2 = (const float*)d_in[11];
    const float* bih2 = (const float*)d_in[12];
    const float* bhh2 = (const float*)d_in[13];
    const float* fcw  = (const float*)d_in[14];
    const float* fcb  = (const float*)d_in[15];
    float* out = (float*)d_out;

    split_w_kernel<<<(HID * IND + 255) / 256, 256>>>(Wih0);
    input_gemm_kernel<<<(BATCH * SEQ) / 64, 128>>>(x, bih0, bhh0);
    rnn_kernel<<<BATCH, 128>>>(Whh0, Wih1, Whh1, bih1, bhh1,
                               Wih2, Whh2, bih2, bhh2, fcw, fcb, out);
}

// round 2
// speedup vs baseline: 1.0038x; 1.0038x over previous
#include <cuda_runtime.h>
#include <cuda_bf16.h>
#include <cstdint>
#include <cstddef>

#define BATCH 128
#define SEQ   512
#define IND   768
#define HID   64

// Scratch (allocation-free rule: __device__ globals)
__device__ float g_pre0[BATCH * SEQ * HID];          // layer-0 pre-activations
__device__ unsigned short g_Whi[HID * IND];          // W_ih0 hi bf16 (truncated)
__device__ unsigned short g_Wlo[HID * IND];          // W_ih0 lo bf16 (rounded residual)

// ---------------------------------------------------------------------------
// Kernel 0: split W_ih0 into bf16 hi/lo
// ---------------------------------------------------------------------------
__global__ void split_w_kernel(const float* __restrict__ W) {
    int i = blockIdx.x * 256 + threadIdx.x;
    if (i < HID * IND) {
        float f = W[i];
        unsigned u = __float_as_uint(f) & 0xFFFF0000u;   // truncate-to-bf16 (exact split)
        g_Whi[i] = (unsigned short)(u >> 16);
        float lo = f - __uint_as_float(u);
        unsigned pair;
        asm("cvt.rn.bf16x2.f32 %0, %1, %2;" : "=r"(pair) : "f"(0.0f), "f"(lo));
        g_Wlo[i] = (unsigned short)(pair & 0xFFFFu);
    }
}

// ---------------------------------------------------------------------------
// Kernel 1: pre0 = x @ W_ih0^T + b_ih0 + b_hh0   via split-bf16 mma.sync
// M = 65536 (B*T), N = 64, K = 768. CTA: 64 M-rows, 4 warps (16 rows each).
// ---------------------------------------------------------------------------
__device__ __forceinline__ void split2(float2 f, uint32_t& hi, uint32_t& lo) {
    uint32_t u0 = __float_as_uint(f.x), u1 = __float_as_uint(f.y);
    hi = __byte_perm(u0, u1, 0x7632);                 // {bf16(f.y),bf16(f.x)} truncated
    float l0 = f.x - __uint_as_float(u0 & 0xFFFF0000u);
    float l1 = f.y - __uint_as_float(u1 & 0xFFFF0000u);
    asm("cvt.rn.bf16x2.f32 %0, %1, %2;" : "=r"(lo) : "f"(l1), "f"(l0));
}

#define MMA4(C, A, Bv)                                                          \
    asm volatile(                                                               \
        "mma.sync.aligned.m16n8k16.row.col.f32.bf16.bf16.f32 "                  \
        "{%0,%1,%2,%3}, {%4,%5,%6,%7}, {%8,%9}, {%0,%1,%2,%3};"                 \
        : "+f"((C)[0]), "+f"((C)[1]), "+f"((C)[2]), "+f"((C)[3])                \
        : "r"((A)[0]), "r"((A)[1]), "r"((A)[2]), "r"((A)[3]),                   \
          "r"((Bv)[0]), "r"((Bv)[1]))

__global__ __launch_bounds__(128) void input_gemm_kernel(
    const float* __restrict__ x,
    const float* __restrict__ bih, const float* __restrict__ bhh)
{
    int tid  = threadIdx.x;
    int warp = tid >> 5, lane = tid & 31;
    int g = lane >> 2, tg = lane & 3;
    int r0 = blockIdx.x * 64 + warp * 16 + g;
    int r1 = r0 + 8;
    const float* xr0 = x + (size_t)r0 * IND;
    const float* xr1 = x + (size_t)r1 * IND;

    float c[8][4];
#pragma unroll
    for (int nt = 0; nt < 8; nt++) { c[nt][0]=0.f; c[nt][1]=0.f; c[nt][2]=0.f; c[nt][3]=0.f; }

    for (int kc = 0; kc < IND; kc += 16) {
        uint32_t ah[4], al[4];
        split2(*(const float2*)(xr0 + kc     + tg*2), ah[0], al[0]);
        split2(*(const float2*)(xr1 + kc     + tg*2), ah[1], al[1]);
        split2(*(const float2*)(xr0 + kc + 8 + tg*2), ah[2], al[2]);
        split2(*(const float2*)(xr1 + kc + 8 + tg*2), ah[3], al[3]);
#pragma unroll
        for (int nt = 0; nt < 8; nt++) {
            int n = nt * 8 + g;
            const unsigned short* whp = g_Whi + n * IND + kc + tg * 2;
            const unsigned short* wlp = g_Wlo + n * IND + kc + tg * 2;
            uint32_t bh[2], bl[2];
            bh[0] = *(const uint32_t*)(whp);
            bh[1] = *(const uint32_t*)(whp + 8);
            bl[0] = *(const uint32_t*)(wlp);
            bl[1] = *(const uint32_t*)(wlp + 8);
            MMA4(c[nt], ah, bh);   // hi*hi
            MMA4(c[nt], al, bh);   // lo*hi
            MMA4(c[nt], ah, bl);   // hi*lo   (lo*lo dropped, ~2^-18)
        }
    }

#pragma unroll
    for (int nt = 0; nt < 8; nt++) {
        int n0 = nt * 8 + tg * 2;
        float bb0 = bih[n0]     + bhh[n0];
        float bb1 = bih[n0 + 1] + bhh[n0 + 1];
        float2 s0 = make_float2(c[nt][0] + bb0, c[nt][1] + bb1);
        float2 s1 = make_float2(c[nt][2] + bb0, c[nt][3] + bb1);
        *(float2*)(g_pre0 + (size_t)r0 * HID + n0) = s0;
        *(float2*)(g_pre0 + (size_t)r1 * HID + n0) = s1;
    }
}

// ---------------------------------------------------------------------------
// Kernel 2: fused 3-layer recurrence, one CTA per batch element.
// 128 threads: thread = 2*j + half; j = output neuron, half = k-range half.
// Weight row-slices live in registers as f32x2 pairs; h in smem (bank-safe).
// ---------------------------------------------------------------------------
typedef unsigned long long ull;

__device__ __forceinline__ ull fma2(ull a, ull b, ull c) {
    ull d; asm("fma.rn.f32x2 %0, %1, %2, %3;" : "=l"(d) : "l"(a), "l"(b), "l"(c)); return d;
}
__device__ __forceinline__ ull add2(ull a, ull b) {
    ull d; asm("add.rn.f32x2 %0, %1, %2;" : "=l"(d) : "l"(a), "l"(b)); return d;
}
__device__ __forceinline__ float red2(ull v) {
    float lo, hi; asm("mov.b64 {%0,%1}, %2;" : "=f"(lo), "=f"(hi) : "l"(v)); return lo + hi;
}
__device__ __forceinline__ ull packf2(float a, float b) {
    ull d; asm("mov.b64 %0, {%1,%2};" : "=l"(d) : "f"(a), "f"(b)); return d;
}

__device__ __forceinline__ void dot32acc(const ull* w, const float* hbase,
                                         ull& a0, ull& a1, ull& a2, ull& a3) {
    const ulonglong2* hp = (const ulonglong2*)hbase;   // 16B-aligned by layout
#pragma unroll
    for (int i = 0; i < 8; i += 2) {
        ulonglong2 u = hp[i];
        a0 = fma2(w[2*i],     u.x, a0);
        a1 = fma2(w[2*i + 1], u.y, a1);
        ulonglong2 v = hp[i + 1];
        a2 = fma2(w[2*i + 2], v.x, a2);
        a3 = fma2(w[2*i + 3], v.y, a3);
    }
}

__global__ __launch_bounds__(128, 1) void rnn_kernel(
    const float* __restrict__ Whh0,
    const float* __restrict__ Wih1, const float* __restrict__ Whh1,
    const float* __restrict__ bih1, const float* __restrict__ bhh1,
    const float* __restrict__ Wih2, const float* __restrict__ Whh2,
    const float* __restrict__ bih2, const float* __restrict__ bhh2,
    const float* __restrict__ fcw,  const float* __restrict__ fcb,
    float* __restrict__ out)
{
    // [layer][parity][half][36]: +36 floats between halves => broadcast groups
    // land in disjoint banks; each half-start is 16B aligned (144B stride).
    __shared__ float hs[3][2][2][36];

    int tid = threadIdx.x;
    int j = tid >> 1, half = tid & 1;
    int b = blockIdx.x;
    int jh = j >> 5, jl = j & 31;

    for (int i = tid; i < 3 * 2 * 2 * 36; i += 128) (&hs[0][0][0][0])[i] = 0.f;

    ull w0[16], wi1[16], wh1[16], wi2[16], wh2[16];
#define LOADW(dst, src) do {                                                    \
        const float4* p4 = (const float4*)((src) + j * HID + half * 32);        \
        _Pragma("unroll")                                                       \
        for (int i = 0; i < 8; i++) {                                           \
            float4 v = p4[i];                                                   \
            (dst)[2*i]     = packf2(v.x, v.y);                                  \
            (dst)[2*i + 1] = packf2(v.z, v.w);                                  \
        }                                                                       \
    } while (0)
    LOADW(w0,  Whh0);
    LOADW(wi1, Wih1);  LOADW(wh1, Whh1);
    LOADW(wi2, Wih2);  LOADW(wh2, Whh2);

    float bias1 = bih1[j] + bhh1[j];
    float bias2 = bih2[j] + bhh2[j];

    const float* preB = g_pre0 + (size_t)b * SEQ * HID;
    float pre_cur = preB[j];
    __syncthreads();

    for (int t = 0; t < SEQ; t++) {
        int p = t & 1, pn = p ^ 1;
        int tn = (t + 1 < SEQ) ? (t + 1) : (SEQ - 1);
        float pre_next = __ldg(preB + tn * HID + j);   // consumed next iter: full-step slack

        // ---- layer 0 ----
        ull a0 = 0, a1 = 0, a2 = 0, a3 = 0;
        dot32acc(w0, &hs[0][p][half][0], a0, a1, a2, a3);
        float d0 = red2(add2(add2(a0, a1), add2(a2, a3)));
        d0 += __shfl_xor_sync(0xFFFFFFFFu, d0, 1);
        float h0n = tanhf(pre_cur + d0);
        hs[0][pn][jh][jl] = h0n;
        __syncthreads();

        // ---- layer 1 ----
        a0 = 0; a1 = 0; a2 = 0; a3 = 0;
        dot32acc(wi1, &hs[0][pn][half][0], a0, a1, a2, a3);
        dot32acc(wh1, &hs[1][p][half][0],  a0, a1, a2, a3);
        float d1 = red2(add2(add2(a0, a1), add2(a2, a3)));
        d1 += __shfl_xor_sync(0xFFFFFFFFu, d1, 1);
        float h1n = tanhf(bias1 + d1);
        hs[1][pn][jh][jl] = h1n;
        __syncthreads();

        // ---- layer 2 ----
        a0 = 0; a1 = 0; a2 = 0; a3 = 0;
        dot32acc(wi2, &hs[1][pn][half][0], a0, a1, a2, a3);
        dot32acc(wh2, &hs[2][p][half][0],  a0, a1, a2, a3);
        float d2 = red2(add2(add2(a0, a1), add2(a2, a3)));
        d2 += __shfl_xor_sync(0xFFFFFFFFu, d2, 1);
        float h2n = tanhf(bias2 + d2);
        hs[2][pn][jh][jl] = h2n;
        __syncthreads();

        pre_cur = pre_next;
    }

    // final h2 (t=511 wrote parity 0) -> out[b] = fc_w . h2 + fc_b
    if (tid < 32) {
        float v0 = hs[2][0][0][tid];
        float v1 = hs[2][0][1][tid];
        float s = fcw[tid] * v0 + fcw[tid + 32] * v1;
#pragma unroll
        for (int o = 16; o; o >>= 1) s += __shfl_xor_sync(0xFFFFFFFFu, s, o);
        if (tid == 0) out[b] = s + fcb[0];
    }
}

// ---------------------------------------------------------------------------
// Launch: split W -> input GEMM -> fused recurrence (default stream, capturable)
// Input order: x, fixation_num, W_ih0, W_hh0, b_ih0, b_hh0, W_ih1, W_hh1,
//              b_ih1, b_hh1, W_ih2, W_hh2, b_ih2, b_hh2, fc_w, fc_b
// ---------------------------------------------------------------------------
extern "C" void kernel_launch(void* const* d_in, const int* in_sizes, int n_in,
                              void* d_out, int out_size)
{
    const float* x    = (const float*)d_in[0];
    const float* Wih0 = (const float*)d_in[2];
    const float* Whh0 = (const float*)d_in[3];
    const float* bih0 = (const float*)d_in[4];
    const float* bhh0 = (const float*)d_in[5];
    const float* Wih1 = (const float*)d_in[6];
    const float* Whh1 = (const float*)d_in[7];
    const float* bih1 = (const float*)d_in[8];
    const float* bhh1 = (const float*)d_in[9];
    const float* Wih2 = (const float*)d_in[10];
    const float* Whh2 = (const float*)d_in[11];
    const float* bih2 = (const float*)d_in[12];
    const float* bhh2 = (const float*)d_in[13];
    const float* fcw  = (const float*)d_in[14];
    const float* fcb  = (const float*)d_in[15];
    float* out = (float*)d_out;

    split_w_kernel<<<(HID * IND + 255) / 256, 256>>>(Wih0);
    input_gemm_kernel<<<(BATCH * SEQ) / 64, 128>>>(x, bih0, bhh0);
    rnn_kernel<<<BATCH, 128>>>(Whh0, Wih1, Whh1, bih1, bhh1,
                               Wih2, Whh2, bih2, bhh2, fcw, fcb, out);
}

// round 3
// speedup vs baseline: 1.5250x; 1.5192x over previous
#include <cuda_runtime.h>
#include <cuda_bf16.h>
#include <cstdint>
#include <cstddef>

#define BATCH 128
#define SEQ   512
#define IND   768
#define HID   64
#define NKC   (IND / 16)       // 48 k-chunks
#define NFRAG (NKC * 8 * 32)   // fragment count * lanes

// Scratch (allocation-free rule: __device__ globals)
__device__ float    g_pre0[BATCH * SEQ * HID];   // layer-0 pre-activations
__device__ uint32_t g_WfragHi[NFRAG * 2];        // W_ih0 hi bf16, mma-B-fragment packed
__device__ uint32_t g_WfragLo[NFRAG * 2];        // W_ih0 lo bf16, mma-B-fragment packed

// ---------------------------------------------------------------------------
// Kernel 0: split W_ih0 into bf16 hi/lo AND pack into mma B-fragment layout.
// Fragment (kcI, nt, lane, r): n = nt*8 + (lane>>2), k = kcI*16 + r*8 + (lane&3)*2
// ---------------------------------------------------------------------------
__global__ void split_w_kernel(const float* __restrict__ W) {
    int idx = blockIdx.x * 256 + threadIdx.x;       // 0 .. NFRAG*2-1
    if (idx >= NFRAG * 2) return;
    int r    = idx & 1;
    int lane = (idx >> 1) & 31;
    int nt   = (idx >> 6) & 7;
    int kcI  = idx >> 9;
    int n = nt * 8 + (lane >> 2);
    int k = kcI * 16 + r * 8 + (lane & 3) * 2;

    float f0 = W[n * IND + k];
    float f1 = W[n * IND + k + 1];
    uint32_t u0 = __float_as_uint(f0), u1 = __float_as_uint(f1);
    g_WfragHi[idx] = __byte_perm(u0, u1, 0x7632);   // truncated-bf16 pair (exact split)
    float l0 = f0 - __uint_as_float(u0 & 0xFFFF0000u);
    float l1 = f1 - __uint_as_float(u1 & 0xFFFF0000u);
    uint32_t lo;
    asm("cvt.rn.bf16x2.f32 %0, %1, %2;" : "=r"(lo) : "f"(l1), "f"(l0));
    g_WfragLo[idx] = lo;
}

// ---------------------------------------------------------------------------
// Kernel 1: pre0 = x @ W_ih0^T + b_ih0 + b_hh0  via split-bf16 mma.sync.
// M = 65536, N = 64, K = 768. CTA: 64 M-rows, 4 warps x 16 rows.
// B-fragments now coalesced LDG.64 from the packed arrays.
// ---------------------------------------------------------------------------
__device__ __forceinline__ void split2(float2 f, uint32_t& hi, uint32_t& lo) {
    uint32_t u0 = __float_as_uint(f.x), u1 = __float_as_uint(f.y);
    hi = __byte_perm(u0, u1, 0x7632);
    float l0 = f.x - __uint_as_float(u0 & 0xFFFF0000u);
    float l1 = f.y - __uint_as_float(u1 & 0xFFFF0000u);
    asm("cvt.rn.bf16x2.f32 %0, %1, %2;" : "=r"(lo) : "f"(l1), "f"(l0));
}

#define MMA4(C, A, B0, B1)                                                      \
    asm volatile(                                                               \
        "mma.sync.aligned.m16n8k16.row.col.f32.bf16.bf16.f32 "                  \
        "{%0,%1,%2,%3}, {%4,%5,%6,%7}, {%8,%9}, {%0,%1,%2,%3};"                 \
        : "+f"((C)[0]), "+f"((C)[1]), "+f"((C)[2]), "+f"((C)[3])                \
        : "r"((A)[0]), "r"((A)[1]), "r"((A)[2]), "r"((A)[3]),                   \
          "r"(B0), "r"(B1))

__global__ __launch_bounds__(128) void input_gemm_kernel(
    const float* __restrict__ x,
    const float* __restrict__ bih, const float* __restrict__ bhh)
{
    int tid  = threadIdx.x;
    int warp = tid >> 5, lane = tid & 31;
    int g = lane >> 2, tg = lane & 3;
    int r0 = blockIdx.x * 64 + warp * 16 + g;
    int r1 = r0 + 8;
    const float* xr0 = x + (size_t)r0 * IND;
    const float* xr1 = x + (size_t)r1 * IND;

    float c[8][4];
#pragma unroll
    for (int nt = 0; nt < 8; nt++) { c[nt][0]=0.f; c[nt][1]=0.f; c[nt][2]=0.f; c[nt][3]=0.f; }

    const uint2* fragHi = (const uint2*)g_WfragHi;
    const uint2* fragLo = (const uint2*)g_WfragLo;

    for (int kcI = 0; kcI < NKC; kcI++) {
        int kc = kcI * 16;
        uint32_t ah[4], al[4];
        split2(*(const float2*)(xr0 + kc     + tg*2), ah[0], al[0]);
        split2(*(const float2*)(xr1 + kc     + tg*2), ah[1], al[1]);
        split2(*(const float2*)(xr0 + kc + 8 + tg*2), ah[2], al[2]);
        split2(*(const float2*)(xr1 + kc + 8 + tg*2), ah[3], al[3]);
#pragma unroll
        for (int nt = 0; nt < 8; nt++) {
            int fidx = (kcI * 8 + nt) * 32 + lane;
            uint2 bh = fragHi[fidx];      // coalesced: 256B/warp, 2 lines
            uint2 bl = fragLo[fidx];
            MMA4(c[nt], ah, bh.x, bh.y);  // hi*hi
            MMA4(c[nt], al, bh.x, bh.y);  // lo*hi
            MMA4(c[nt], ah, bl.x, bl.y);  // hi*lo  (lo*lo dropped, ~2^-18)
        }
    }

#pragma unroll
    for (int nt = 0; nt < 8; nt++) {
        int n0 = nt * 8 + tg * 2;
        float bb0 = bih[n0]     + bhh[n0];
        float bb1 = bih[n0 + 1] + bhh[n0 + 1];
        float2 s0 = make_float2(c[nt][0] + bb0, c[nt][1] + bb1);
        float2 s1 = make_float2(c[nt][2] + bb0, c[nt][3] + bb1);
        *(float2*)(g_pre0 + (size_t)r0 * HID + n0) = s0;
        *(float2*)(g_pre0 + (size_t)r1 * HID + n0) = s1;
    }
}

// ---------------------------------------------------------------------------
// Kernel 2: fused 3-layer recurrence, layers software-pipelined across 3
// warpgroups (384 threads). One __syncthreads per step; per-step critical
// path = one layer, not three.
// ---------------------------------------------------------------------------
typedef unsigned long long ull;

__device__ __forceinline__ ull fma2(ull a, ull b, ull c) {
    ull d; asm("fma.rn.f32x2 %0, %1, %2, %3;" : "=l"(d) : "l"(a), "l"(b), "l"(c)); return d;
}
__device__ __forceinline__ ull add2(ull a, ull b) {
    ull d; asm("add.rn.f32x2 %0, %1, %2;" : "=l"(d) : "l"(a), "l"(b)); return d;
}
__device__ __forceinline__ float red2(ull v) {
    float lo, hi; asm("mov.b64 {%0,%1}, %2;" : "=f"(lo), "=f"(hi) : "l"(v)); return lo + hi;
}
__device__ __forceinline__ ull packf2(float a, float b) {
    ull d; asm("mov.b64 %0, {%1,%2};" : "=l"(d) : "f"(a), "f"(b)); return d;
}

// tanh(x) = (e^{2x}-1)/(e^{2x}+1) via ex2.approx + rcp.approx; |err| ~ 1e-6.
__device__ __forceinline__ float fast_tanh(float x) {
    x = fminf(fmaxf(x, -9.0f), 9.0f);               // keep e^{2x} finite
    float e;
    asm("{ .reg .f32 t;\n\t"
        "  mul.f32 t, %1, 0f4038AA3B;\n\t"          // 2*log2(e)
        "  ex2.approx.f32 %0, t; }"
        : "=f"(e) : "f"(x));
    float r;
    asm("rcp.approx.f32 %0, %1;" : "=f"(r) : "f"(e + 1.0f));
    return (e - 1.0f) * r;
}

__device__ __forceinline__ void dot32acc(const ull* w, const float* hbase,
                                         ull& a0, ull& a1, ull& a2, ull& a3) {
    const ulonglong2* hp = (const ulonglong2*)hbase;   // 16B aligned (144B stride)
#pragma unroll
    for (int i = 0; i < 8; i += 2) {
        ulonglong2 u = hp[i];
        a0 = fma2(w[2*i],     u.x, a0);
        a1 = fma2(w[2*i + 1], u.y, a1);
        ulonglong2 v = hp[i + 1];
        a2 = fma2(w[2*i + 2], v.x, a2);
        a3 = fma2(w[2*i + 3], v.y, a3);
    }
}

__global__ __launch_bounds__(384, 1) void rnn_kernel(
    const float* __restrict__ Whh0,
    const float* __restrict__ Wih1, const float* __restrict__ Whh1,
    const float* __restrict__ bih1, const float* __restrict__ bhh1,
    const float* __restrict__ Wih2, const float* __restrict__ Whh2,
    const float* __restrict__ bih2, const float* __restrict__ bhh2,
    const float* __restrict__ fcw,  const float* __restrict__ fcb,
    float* __restrict__ out)
{
    // hs[layer][slot][half][36]: h_l[t] lives in slot t&1. +36 offset keeps the
    // two 16-lane broadcast groups in disjoint banks; half-starts 16B aligned.
    __shared__ float hs[3][2][2][36];

    int tid = threadIdx.x;
    int wg  = tid >> 7;            // warpgroup = layer (0,1,2)
    int wt  = tid & 127;
    int j = wt >> 1, half = wt & 1;
    int jh = j >> 5, jl = j & 31;
    int b = blockIdx.x;

    for (int i = tid; i < 3 * 2 * 2 * 36; i += 384) (&hs[0][0][0][0])[i] = 0.f;

    ull wa[16], wb[16];
    float bias = 0.f;
#define LOADW(dst, src) do {                                                    \
        const float4* p4 = (const float4*)((src) + j * HID + half * 32);        \
        _Pragma("unroll")                                                       \
        for (int i = 0; i < 8; i++) {                                           \
            float4 v = p4[i];                                                   \
            (dst)[2*i]     = packf2(v.x, v.y);                                  \
            (dst)[2*i + 1] = packf2(v.z, v.w);                                  \
        }                                                                       \
    } while (0)
    if (wg == 0) {
        LOADW(wa, Whh0);
    } else if (wg == 1) {
        LOADW(wa, Wih1); LOADW(wb, Whh1); bias = bih1[j] + bhh1[j];
    } else {
        LOADW(wa, Wih2); LOADW(wb, Whh2); bias = bih2[j] + bhh2[j];
    }

    const float* preB = g_pre0 + (size_t)b * SEQ * HID;
    float pre_cur = (wg == 0) ? preB[j] : 0.f;
    __syncthreads();

    for (int s = 0; s < SEQ + 2; s++) {
        if (wg == 0) {
            if (s < SEQ) {
                int t = s;
                int tn = (t + 1 < SEQ) ? (t + 1) : (SEQ - 1);
                float pre_next = __ldg(preB + tn * HID + j);  // full-step slack
                ull a0 = 0, a1 = 0, a2 = 0, a3 = 0;
                dot32acc(wa, &hs[0][(t + 1) & 1][half][0], a0, a1, a2, a3);
                float d = red2(add2(add2(a0, a1), add2(a2, a3)));
                d += __shfl_xor_sync(0xFFFFFFFFu, d, 1);
                hs[0][t & 1][jh][jl] = fast_tanh(pre_cur + d);
                pre_cur = pre_next;
            }
        } else if (wg == 1) {
            if (s >= 1 && s <= SEQ) {
                int t = s - 1;
                ull a0=0,a1=0,a2=0,a3=0, c0=0,c1=0,c2=0,c3=0;
                dot32acc(wa, &hs[0][t & 1][half][0],       a0, a1, a2, a3);
                dot32acc(wb, &hs[1][(t + 1) & 1][half][0], c0, c1, c2, c3);
                float d = red2(add2(add2(add2(a0,c0), add2(a1,c1)),
                                    add2(add2(a2,c2), add2(a3,c3))));
                d += __shfl_xor_sync(0xFFFFFFFFu, d, 1);
                hs[1][t & 1][jh][jl] = fast_tanh(bias + d);
            }
        } else {
            if (s >= 2) {
                int t = s - 2;
                ull a0=0,a1=0,a2=0,a3=0, c0=0,c1=0,c2=0,c3=0;
                dot32acc(wa, &hs[1][t & 1][half][0],       a0, a1, a2, a3);
                dot32acc(wb, &hs[2][(t + 1) & 1][half][0], c0, c1, c2, c3);
                float d = red2(add2(add2(add2(a0,c0), add2(a1,c1)),
                                    add2(add2(a2,c2), add2(a3,c3))));
                d += __shfl_xor_sync(0xFFFFFFFFu, d, 1);
                hs[2][t & 1][jh][jl] = fast_tanh(bias + d);
            }
        }
        __syncthreads();
    }

    // h2[511] is in slot 1.  out[b] = fc_w . h2 + fc_b  (warp 8 = wg2 lanes)
    if (tid >= 256 && tid < 288) {
        int l = tid - 256;
        float v0 = hs[2][1][0][l];
        float v1 = hs[2][1][1][l];
        float sacc = fcw[l] * v0 + fcw[l + 32] * v1;
#pragma unroll
        for (int o = 16; o; o >>= 1) sacc += __shfl_xor_sync(0xFFFFFFFFu, sacc, o);
        if (l == 0) out[b] = sacc + fcb[0];
    }
}

// ---------------------------------------------------------------------------
// Launch. Input order: x, fixation_num, W_ih0, W_hh0, b_ih0, b_hh0, W_ih1,
// W_hh1, b_ih1, b_hh1, W_ih2, W_hh2, b_ih2, b_hh2, fc_w, fc_b
// ---------------------------------------------------------------------------
extern "C" void kernel_launch(void* const* d_in, const int* in_sizes, int n_in,
                              void* d_out, int out_size)
{
    const float* x    = (const float*)d_in[0];
    const float* Wih0 = (const float*)d_in[2];
    const float* Whh0 = (const float*)d_in[3];
    const float* bih0 = (const float*)d_in[4];
    const float* bhh0 = (const float*)d_in[5];
    const float* Wih1 = (const float*)d_in[6];
    const float* Whh1 = (const float*)d_in[7];
    const float* bih1 = (const float*)d_in[8];
    const float* bhh1 = (const float*)d_in[9];
    const float* Wih2 = (const float*)d_in[10];
    const float* Whh2 = (const float*)d_in[11];
    const float* bih2 = (const float*)d_in[12];
    const float* bhh2 = (const float*)d_in[13];
    const float* fcw  = (const float*)d_in[14];
    const float* fcb  = (const float*)d_in[15];
    float* out = (float*)d_out;

    split_w_kernel<<<(NFRAG * 2 + 255) / 256, 256>>>(Wih0);
    input_gemm_kernel<<<(BATCH * SEQ) / 64, 128>>>(x, bih0, bhh0);
    rnn_kernel<<<BATCH, 384>>>(Whh0, Wih1, Whh1, bih1, bhh1,
                               Wih2, Whh2, bih2, bhh2, fcw, fcb, out);
}

// round 4
// speedup vs baseline: 1.6856x; 1.1053x over previous
#include <cuda_runtime.h>
#include <cuda_bf16.h>
#include <cstdint>
#include <cstddef>

#define BATCH 128
#define SEQ   512
#define IND   768
#define HID   64
#define NKC   (IND / 16)       // 48 k-chunks
#define NFRAG (NKC * 8 * 32)   // fragment count * lanes

// Scratch (allocation-free rule: __device__ globals). +HID pad: the recurrence
// prefetches pre[t+1] unconditionally, including t=511 of the last batch.
__device__ float    g_pre0[BATCH * SEQ * HID + HID];
__device__ uint32_t g_WfragHi[NFRAG * 2];        // W_ih0 hi bf16, mma-B packed
__device__ uint32_t g_WfragLo[NFRAG * 2];        // W_ih0 lo bf16, mma-B packed

// ---------------------------------------------------------------------------
// Kernel 0: split W_ih0 into bf16 hi/lo AND pack into mma B-fragment layout.
// Fragment (kcI, nt, lane, r): n = nt*8 + (lane>>2), k = kcI*16 + r*8 + (lane&3)*2
// ---------------------------------------------------------------------------
__global__ void split_w_kernel(const float* __restrict__ W) {
    int idx = blockIdx.x * 256 + threadIdx.x;       // 0 .. NFRAG*2-1
    if (idx >= NFRAG * 2) return;
    int r    = idx & 1;
    int lane = (idx >> 1) & 31;
    int nt   = (idx >> 6) & 7;
    int kcI  = idx >> 9;
    int n = nt * 8 + (lane >> 2);
    int k = kcI * 16 + r * 8 + (lane & 3) * 2;

    float f0 = W[n * IND + k];
    float f1 = W[n * IND + k + 1];
    uint32_t u0 = __float_as_uint(f0), u1 = __float_as_uint(f1);
    g_WfragHi[idx] = __byte_perm(u0, u1, 0x7632);   // truncated-bf16 pair (exact split)
    float l0 = f0 - __uint_as_float(u0 & 0xFFFF0000u);
    float l1 = f1 - __uint_as_float(u1 & 0xFFFF0000u);
    uint32_t lo;
    asm("cvt.rn.bf16x2.f32 %0, %1, %2;" : "=r"(lo) : "f"(l1), "f"(l0));
    g_WfragLo[idx] = lo;
}

// ---------------------------------------------------------------------------
// Kernel 1: pre0 = x @ W_ih0^T + b_ih0 + b_hh0  via split-bf16 mma.sync.
// M = 65536, N = 64, K = 768. CTA = 128 rows, 4 warps x 32 rows (M=32/warp:
// two A-fragment sets amortize every B-fragment load).
// ---------------------------------------------------------------------------
__device__ __forceinline__ void split2(float2 f, uint32_t& hi, uint32_t& lo) {
    uint32_t u0 = __float_as_uint(f.x), u1 = __float_as_uint(f.y);
    hi = __byte_perm(u0, u1, 0x7632);
    float l0 = f.x - __uint_as_float(u0 & 0xFFFF0000u);
    float l1 = f.y - __uint_as_float(u1 & 0xFFFF0000u);
    asm("cvt.rn.bf16x2.f32 %0, %1, %2;" : "=r"(lo) : "f"(l1), "f"(l0));
}

#define MMA4(C, A, B0, B1)                                                      \
    asm volatile(                                                               \
        "mma.sync.aligned.m16n8k16.row.col.f32.bf16.bf16.f32 "                  \
        "{%0,%1,%2,%3}, {%4,%5,%6,%7}, {%8,%9}, {%0,%1,%2,%3};"                 \
        : "+f"((C)[0]), "+f"((C)[1]), "+f"((C)[2]), "+f"((C)[3])                \
        : "r"((A)[0]), "r"((A)[1]), "r"((A)[2]), "r"((A)[3]),                   \
          "r"(B0), "r"(B1))

__global__ __launch_bounds__(128) void input_gemm_kernel(
    const float* __restrict__ x,
    const float* __restrict__ bih, const float* __restrict__ bhh)
{
    int tid  = threadIdx.x;
    int warp = tid >> 5, lane = tid & 31;
    int g = lane >> 2, tg = lane & 3;
    int base = blockIdx.x * 128 + warp * 32;
    const float* xr0 = x + (size_t)(base + g)      * IND + tg * 2;
    const float* xr1 = x + (size_t)(base + g + 8)  * IND + tg * 2;
    const float* xr2 = x + (size_t)(base + g + 16) * IND + tg * 2;
    const float* xr3 = x + (size_t)(base + g + 24) * IND + tg * 2;

    float c0[8][4], c1[8][4];
#pragma unroll
    for (int nt = 0; nt < 8; nt++)
#pragma unroll
        for (int i = 0; i < 4; i++) { c0[nt][i] = 0.f; c1[nt][i] = 0.f; }

    const uint2* fragHi = (const uint2*)g_WfragHi;
    const uint2* fragLo = (const uint2*)g_WfragLo;

    for (int kcI = 0; kcI < NKC; kcI++) {
        int kc = kcI * 16;
        uint32_t ah0[4], al0[4], ah1[4], al1[4];
        split2(*(const float2*)(xr0 + kc),     ah0[0], al0[0]);
        split2(*(const float2*)(xr1 + kc),     ah0[1], al0[1]);
        split2(*(const float2*)(xr0 + kc + 8), ah0[2], al0[2]);
        split2(*(const float2*)(xr1 + kc + 8), ah0[3], al0[3]);
        split2(*(const float2*)(xr2 + kc),     ah1[0], al1[0]);
        split2(*(const float2*)(xr3 + kc),     ah1[1], al1[1]);
        split2(*(const float2*)(xr2 + kc + 8), ah1[2], al1[2]);
        split2(*(const float2*)(xr3 + kc + 8), ah1[3], al1[3]);
#pragma unroll
        for (int nt = 0; nt < 8; nt++) {
            int fidx = (kcI * 8 + nt) * 32 + lane;
            uint2 bh = fragHi[fidx];      // coalesced 256B/warp
            uint2 bl = fragLo[fidx];
            MMA4(c0[nt], ah0, bh.x, bh.y);
            MMA4(c1[nt], ah1, bh.x, bh.y);
            MMA4(c0[nt], al0, bh.x, bh.y);
            MMA4(c1[nt], al1, bh.x, bh.y);
            MMA4(c0[nt], ah0, bl.x, bl.y);
            MMA4(c1[nt], ah1, bl.x, bl.y);
        }
    }

#pragma unroll
    for (int nt = 0; nt < 8; nt++) {
        int n0 = nt * 8 + tg * 2;
        float bb0 = bih[n0]     + bhh[n0];
        float bb1 = bih[n0 + 1] + bhh[n0 + 1];
        *(float2*)(g_pre0 + (size_t)(base + g)      * HID + n0) = make_float2(c0[nt][0] + bb0, c0[nt][1] + bb1);
        *(float2*)(g_pre0 + (size_t)(base + g + 8)  * HID + n0) = make_float2(c0[nt][2] + bb0, c0[nt][3] + bb1);
        *(float2*)(g_pre0 + (size_t)(base + g + 16) * HID + n0) = make_float2(c1[nt][0] + bb0, c1[nt][1] + bb1);
        *(float2*)(g_pre0 + (size_t)(base + g + 24) * HID + n0) = make_float2(c1[nt][2] + bb0, c1[nt][3] + bb1);
    }
}

// ---------------------------------------------------------------------------
// Kernel 2: fused 3-layer recurrence. Warp-specialized: each warpgroup owns a
// private time loop (unrolled x2, compile-time slot parity, zero per-step
// guards), rendezvous via bar.sync 0,384 once per pipeline step.
// ---------------------------------------------------------------------------
typedef unsigned long long ull;

__device__ __forceinline__ ull fma2(ull a, ull b, ull c) {
    ull d; asm("fma.rn.f32x2 %0, %1, %2, %3;" : "=l"(d) : "l"(a), "l"(b), "l"(c)); return d;
}
__device__ __forceinline__ ull add2(ull a, ull b) {
    ull d; asm("add.rn.f32x2 %0, %1, %2;" : "=l"(d) : "l"(a), "l"(b)); return d;
}
__device__ __forceinline__ float red2(ull v) {
    float lo, hi; asm("mov.b64 {%0,%1}, %2;" : "=f"(lo), "=f"(hi) : "l"(v)); return lo + hi;
}
__device__ __forceinline__ ull packf2(float a, float b) {
    ull d; asm("mov.b64 %0, {%1,%2};" : "=l"(d) : "f"(a), "f"(b)); return d;
}

// tanh via ex2.approx + rcp.approx; |err| ~1e-6 (validated: rel_err 1.04e-5).
__device__ __forceinline__ float fast_tanh(float x) {
    x = fminf(fmaxf(x, -15.0f), 15.0f);
    float e;
    asm("{ .reg .f32 t;\n\t"
        "  mul.f32 t, %1, 0f4038AA3B;\n\t"          // 2*log2(e)
        "  ex2.approx.f32 %0, t; }"
        : "=f"(e) : "f"(x));
    float r;
    asm("rcp.approx.f32 %0, %1;" : "=f"(r) : "f"(e + 1.0f));
    return (e - 1.0f) * r;
}

__device__ __forceinline__ void dot32acc(const ull* w, const float* hbase,
                                         ull& a0, ull& a1, ull& a2, ull& a3) {
    const ulonglong2* hp = (const ulonglong2*)hbase;   // 16B aligned (144B stride)
#pragma unroll
    for (int i = 0; i < 8; i += 2) {
        ulonglong2 u = hp[i];
        a0 = fma2(w[2*i],     u.x, a0);
        a1 = fma2(w[2*i + 1], u.y, a1);
        ulonglong2 v = hp[i + 1];
        a2 = fma2(w[2*i + 2], v.x, a2);
        a3 = fma2(w[2*i + 3], v.y, a3);
    }
}

#define BARALL() asm volatile("bar.sync 0, 384;" ::: "memory")

__global__ __launch_bounds__(384, 1) void rnn_kernel(
    const float* __restrict__ Whh0,
    const float* __restrict__ Wih1, const float* __restrict__ Whh1,
    const float* __restrict__ bih1, const float* __restrict__ bhh1,
    const float* __restrict__ Wih2, const float* __restrict__ Whh2,
    const float* __restrict__ bih2, const float* __restrict__ bhh2,
    const float* __restrict__ fcw,  const float* __restrict__ fcb,
    float* __restrict__ out)
{
    // hs[layer][slot][half][36]: +36 keeps the two 16-lane broadcast groups in
    // disjoint banks; every half-start is 16B aligned (144B stride).
    __shared__ __align__(16) float hs[3][2][2][36];

    int tid = threadIdx.x;
    int wg  = tid >> 7;            // warpgroup = layer (0,1,2)
    int wt  = tid & 127;
    int j = wt >> 1, half = wt & 1;
    int jh = j >> 5, jl = j & 31;
    int b = blockIdx.x;

    for (int i = tid; i < 3 * 2 * 2 * 36; i += 384) (&hs[0][0][0][0])[i] = 0.f;

    ull wa[16], wb[16];
    float bias = 0.f;
#define LOADW(dst, src) do {                                                    \
        const float4* p4 = (const float4*)((src) + j * HID + half * 32);        \
        _Pragma("unroll")                                                       \
        for (int i = 0; i < 8; i++) {                                           \
            float4 v = p4[i];                                                   \
            (dst)[2*i]     = packf2(v.x, v.y);                                  \
            (dst)[2*i + 1] = packf2(v.z, v.w);                                  \
        }                                                                       \
    } while (0)

    const float* prePtr = g_pre0 + (size_t)b * SEQ * HID + j;
    float pre_cur = 0.f;

    if (wg == 0) {
        LOADW(wa, Whh0);
        pre_cur = __ldg(prePtr);
        prePtr += HID;
    } else if (wg == 1) {
        LOADW(wa, Wih1); LOADW(wb, Whh1); bias = bih1[j] + bhh1[j];
    } else {
        LOADW(wa, Wih2); LOADW(wb, Whh2); bias = bih2[j] + bhh2[j];
    }
    __syncthreads();

    // STEP0(P): layer0 at time t with parity P. Reads own h0 slot P^1,
    // writes slot P. Prefetches next pre (padded array => no clamp).
#define STEP0(P) do {                                                           \
        float pre_next = __ldg(prePtr); prePtr += HID;                          \
        ull a0 = 0, a1 = 0, a2 = 0, a3 = 0;                                     \
        dot32acc(wa, &hs[0][(P)^1][half][0], a0, a1, a2, a3);                   \
        float d = red2(add2(add2(a0, a1), add2(a2, a3)));                       \
        d += __shfl_xor_sync(0xFFFFFFFFu, d, 1);                                \
        hs[0][P][jh][jl] = fast_tanh(pre_cur + d);                              \
        pre_cur = pre_next;                                                     \
    } while (0)

    // STEP1(P): layer1 at time t (parity P): reads h0 slot P + own h1 slot P^1.
#define STEP1(P) do {                                                           \
        ull a0=0,a1=0,a2=0,a3=0, c0=0,c1=0,c2=0,c3=0;                           \
        dot32acc(wa, &hs[0][P][half][0],     a0, a1, a2, a3);                   \
        dot32acc(wb, &hs[1][(P)^1][half][0], c0, c1, c2, c3);                   \
        float d = red2(add2(add2(add2(a0,c0), add2(a1,c1)),                     \
                            add2(add2(a2,c2), add2(a3,c3))));                   \
        d += __shfl_xor_sync(0xFFFFFFFFu, d, 1);                                \
        hs[1][P][jh][jl] = fast_tanh(bias + d);                                 \
    } while (0)

#define STEP2(P) do {                                                           \
        ull a0=0,a1=0,a2=0,a3=0, c0=0,c1=0,c2=0,c3=0;                           \
        dot32acc(wa, &hs[1][P][half][0],     a0, a1, a2, a3);                   \
        dot32acc(wb, &hs[2][(P)^1][half][0], c0, c1, c2, c3);                   \
        float d = red2(add2(add2(add2(a0,c0), add2(a1,c1)),                     \
                            add2(add2(a2,c2), add2(a3,c3))));                   \
        d += __shfl_xor_sync(0xFFFFFFFFu, d, 1);                                \
        hs[2][P][jh][jl] = fast_tanh(bias + d);                                 \
    } while (0)

    // Global pipeline step s = 0..513; wg0 runs t=s, wg1 t=s-1, wg2 t=s-2.
    // Every warpgroup executes exactly 514 BARALL()s, in lockstep.
    if (wg == 0) {
        STEP0(0); BARALL();                       // s=0   (t=0)
        STEP0(1); BARALL();                       // s=1   (t=1)
#pragma unroll 1
        for (int it = 0; it < 255; it++) {        // s=2..511 (t=2..511)
            STEP0(0); BARALL();
            STEP0(1); BARALL();
        }
        BARALL();                                 // s=512 (idle)
        BARALL();                                 // s=513 (idle)
    } else if (wg == 1) {
        BARALL();                                 // s=0   (idle)
        STEP1(0); BARALL();                       // s=1   (t=0)
#pragma unroll 1
        for (int it = 0; it < 255; it++) {        // s=2..511 (t=1..510)
            STEP1(1); BARALL();
            STEP1(0); BARALL();
        }
        STEP1(1); BARALL();                       // s=512 (t=511)
        BARALL();                                 // s=513 (idle)
    } else {
        BARALL();                                 // s=0   (idle)
        BARALL();                                 // s=1   (idle)
#pragma unroll 1
        for (int it = 0; it < 255; it++) {        // s=2..511 (t=0..509)
            STEP2(0); BARALL();
            STEP2(1); BARALL();
        }
        STEP2(0); BARALL();                       // s=512 (t=510)
        STEP2(1); BARALL();                       // s=513 (t=511)
    }

    // h2[511] lives in slot 1 (visible: last BARALL followed wg2's final write).
    if (tid >= 256 && tid < 288) {
        int l = tid - 256;
        float v0 = hs[2][1][0][l];
        float v1 = hs[2][1][1][l];
        float sacc = fcw[l] * v0 + fcw[l + 32] * v1;
#pragma unroll
        for (int o = 16; o; o >>= 1) sacc += __shfl_xor_sync(0xFFFFFFFFu, sacc, o);
        if (l == 0) out[b] = sacc + fcb[0];
    }
}

// ---------------------------------------------------------------------------
// Launch. Input order: x, fixation_num, W_ih0, W_hh0, b_ih0, b_hh0, W_ih1,
// W_hh1, b_ih1, b_hh1, W_ih2, W_hh2, b_ih2, b_hh2, fc_w, fc_b
// ---------------------------------------------------------------------------
extern "C" void kernel_launch(void* const* d_in, const int* in_sizes, int n_in,
                              void* d_out, int out_size)
{
    const float* x    = (const float*)d_in[0];
    const float* Wih0 = (const float*)d_in[2];
    const float* Whh0 = (const float*)d_in[3];
    const float* bih0 = (const float*)d_in[4];
    const float* bhh0 = (const float*)d_in[5];
    const float* Wih1 = (const float*)d_in[6];
    const float* Whh1 = (const float*)d_in[7];
    const float* bih1 = (const float*)d_in[8];
    const float* bhh1 = (const float*)d_in[9];
    const float* Wih2 = (const float*)d_in[10];
    const float* Whh2 = (const float*)d_in[11];
    const float* bih2 = (const float*)d_in[12];
    const float* bhh2 = (const float*)d_in[13];
    const float* fcw  = (const float*)d_in[14];
    const float* fcb  = (const float*)d_in[15];
    float* out = (float*)d_out;

    split_w_kernel<<<(NFRAG * 2 + 255) / 256, 256>>>(Wih0);
    input_gemm_kernel<<<(BATCH * SEQ) / 128, 128>>>(x, bih0, bhh0);
    rnn_kernel<<<BATCH, 384>>>(Whh0, Wih1, Whh1, bih1, bhh1,
                               Wih2, Whh2, bih2, bhh2, fcw, fcb, out);
}